// round 8
// baseline (speedup 1.0000x reference)
#include <cuda_runtime.h>

// Thole dipole-dipole interaction tensor.
//   t[e] = 3*lambda5*inv_r5 * v v^T  -  lambda3*inv_r3 * I3
// Inputs (metadata order): species(i32,N) [unused], edge_src(i32,E),
// edge_dst(i32,E), distances(f32,E), vec(f32,3E), polarisability(f32,N).
// Output: f32, E*9.
//
// R5 ncu: latency-bound (issue 14.9%, DRAM 30%, L1 48%, occ 93%).
// L1tex wavefront floor ~60-70us set by 12.8M random pol-gather wavefronts.
// This version maximizes in-flight loads: ITEMS=3 per thread, all 24 loads
// (3 dist + 6 idx + 9 vec + 6 pol gathers) batched before compute.
// Output transposed through smem (stride-9, conflict-free) -> float4 stores.

#define BOHR_F 0.52917721067f
#define A_MUTUAL_F 0.39f

static constexpr int TPB   = 256;
static constexpr int ITEMS = 3;
static constexpr int EPB   = TPB * ITEMS;            // 768 edges per block
static constexpr int OUT_F4 = EPB * 9 / 4;           // 1728 float4 staged out

__global__ __launch_bounds__(TPB, 6)
void polarisation_kernel(const int* __restrict__ edge_src,
                         const int* __restrict__ edge_dst,
                         const float* __restrict__ distances,
                         const float* __restrict__ vec,
                         const float* __restrict__ pol,
                         float* __restrict__ out,
                         int E) {
    __shared__ float4 s_out4[OUT_F4];   // 27 KB -> 6 CTAs/SM
    float* s_out = (float*)s_out4;

    const int tid = threadIdx.x;
    const int block_start = blockIdx.x * EPB;

    const float inv_bohr = 1.0f / BOHR_F;
    const float inv_b6 = inv_bohr * inv_bohr * inv_bohr *
                         inv_bohr * inv_bohr * inv_bohr;

    if (block_start + EPB <= E) {
        // ---------- fast path: batch ALL loads, then gathers, then compute ----
        float rr[ITEMS];
        int   si[ITEMS], di[ITEMS];
        float vv[ITEMS * 3];

        #pragma unroll
        for (int j = 0; j < ITEMS; j++) {
            const int e = block_start + tid + j * TPB;
            rr[j] = __ldcs(&distances[e]);
            si[j] = __ldcs(&edge_src[e]);
            di[j] = __ldcs(&edge_dst[e]);
            vv[j * 3 + 0] = __ldcs(&vec[e * 3 + 0]);
            vv[j * 3 + 1] = __ldcs(&vec[e * 3 + 1]);
            vv[j * 3 + 2] = __ldcs(&vec[e * 3 + 2]);
        }

        float ps[ITEMS], pd[ITEMS];
        #pragma unroll
        for (int j = 0; j < ITEMS; j++) {
            ps[j] = __ldg(&pol[si[j]]);   // pol stays L2-resident (not streamed)
            pd[j] = __ldg(&pol[di[j]]);
        }

        #pragma unroll
        for (int j = 0; j < ITEMS; j++) {
            const float r  = rr[j] * inv_bohr;
            const float vx = vv[j * 3 + 0] * inv_bohr;
            const float vy = vv[j * 3 + 1] * inv_bohr;
            const float vz = vv[j * 3 + 2] * inv_bohr;
            const float alpha_ij = ps[j] * pd[j] * inv_b6;

            const float inv_r  = __fdividef(1.0f, r);
            const float inv_r2 = inv_r * inv_r;
            const float inv_r3 = inv_r2 * inv_r;
            const float inv_r5 = inv_r3 * inv_r2;

            // a*u^3 = a * r^3 / sqrt(alpha_ij)  (== a*(r/alpha^(1/6))^3)
            const float au3 = A_MUTUAL_F * (r * r * r) * rsqrtf(alpha_ij);
            const float ex  = __expf(-au3);
            const float lambda3 = 1.0f - ex;
            const float lambda5 = 1.0f - (1.0f + au3) * ex;

            const float c5 = 3.0f * lambda5 * inv_r5;
            const float c3 = lambda3 * inv_r3;

            // stride-9 smem writes: gcd(9,32)=1 -> conflict-free
            float* o = &s_out[(tid + j * TPB) * 9];
            o[0] = c5 * vx * vx - c3;
            o[1] = c5 * vx * vy;
            o[2] = c5 * vx * vz;
            o[3] = c5 * vy * vx;
            o[4] = c5 * vy * vy - c3;
            o[5] = c5 * vy * vz;
            o[6] = c5 * vz * vx;
            o[7] = c5 * vz * vy;
            o[8] = c5 * vz * vz - c3;
        }
    } else {
        // ---------- tail path: per-item guarded ----------
        #pragma unroll
        for (int j = 0; j < ITEMS; j++) {
            const int le = tid + j * TPB;
            const int e  = block_start + le;
            if (e < E) {
                const float r  = distances[e] * inv_bohr;
                const float vx = vec[e * 3 + 0] * inv_bohr;
                const float vy = vec[e * 3 + 1] * inv_bohr;
                const float vz = vec[e * 3 + 2] * inv_bohr;
                const float alpha_ij = __ldg(&pol[edge_src[e]]) *
                                       __ldg(&pol[edge_dst[e]]) * inv_b6;

                const float inv_r  = __fdividef(1.0f, r);
                const float inv_r2 = inv_r * inv_r;
                const float inv_r3 = inv_r2 * inv_r;
                const float inv_r5 = inv_r3 * inv_r2;

                const float au3 = A_MUTUAL_F * (r * r * r) * rsqrtf(alpha_ij);
                const float ex  = __expf(-au3);
                const float lambda3 = 1.0f - ex;
                const float lambda5 = 1.0f - (1.0f + au3) * ex;

                const float c5 = 3.0f * lambda5 * inv_r5;
                const float c3 = lambda3 * inv_r3;

                float* o = &s_out[le * 9];
                o[0] = c5 * vx * vx - c3;
                o[1] = c5 * vx * vy;
                o[2] = c5 * vx * vz;
                o[3] = c5 * vy * vx;
                o[4] = c5 * vy * vy - c3;
                o[5] = c5 * vy * vz;
                o[6] = c5 * vz * vx;
                o[7] = c5 * vz * vy;
                o[8] = c5 * vz * vz - c3;
            }
        }
    }
    __syncthreads();

    // ---------- coalesced 128-bit evict-first stores of EPB*9 floats ----------
    {
        const long long obase4 = (long long)block_start * 9 / 4; // float4 base
        const long long olimit = (long long)E * 9;               // float limit
        #pragma unroll
        for (int k = 0; k < (OUT_F4 + TPB - 1) / TPB; k++) {
            const int idx = tid + k * TPB;
            if (idx < OUT_F4) {
                const long long gf = (obase4 + idx) * 4;
                if (gf + 3 < olimit) {
                    __stcs(&((float4*)out)[obase4 + idx], s_out4[idx]);
                } else {
                    #pragma unroll
                    for (int j = 0; j < 4; j++)
                        if (gf + j < olimit) __stcs(&out[gf + j], s_out[idx * 4 + j]);
                }
            }
        }
    }
}

extern "C" void kernel_launch(void* const* d_in, const int* in_sizes, int n_in,
                              void* d_out, int out_size) {
    // metadata order: species, edge_src, edge_dst, distances, vec, polarisability
    const int*   edge_src = (const int*)d_in[1];
    const int*   edge_dst = (const int*)d_in[2];
    const float* dist     = (const float*)d_in[3];
    const float* vec      = (const float*)d_in[4];
    const float* pol      = (const float*)d_in[5];
    float* out = (float*)d_out;

    const int E = in_sizes[1];
    const int blocks = (E + EPB - 1) / EPB;
    polarisation_kernel<<<blocks, TPB>>>(edge_src, edge_dst, dist, vec, pol, out, E);
}

// round 16
// speedup vs baseline: 1.7939x; 1.7939x over previous
#include <cuda_runtime.h>

// Thole dipole-dipole interaction tensor.
//   t[e] = 3*lambda5*inv_r5 * v v^T  -  lambda3*inv_r3 * I3
// Inputs (metadata order): species(i32,N) [unused], edge_src(i32,E),
// edge_dst(i32,E), distances(f32,E), vec(f32,3E), polarisability(f32,N).
// Output: f32, E*9.
//
// R5: 139.8us (issue 14.9%, DRAM 30%) latency-bound. R8 (front-batched +
// CTA barriers): 159.3us REGRESSION -> scoreboard max-wait + barrier convoy.
// This version: NO __syncthreads. Warp-private smem slab for the output
// transpose (warp writes stride-9, __syncwarp, stores 144 contiguous f4).
// Warps drift independently -> cross-warp pipelining hides gather latency.

#define BOHR_F 0.52917721067f
#define A_MUTUAL_F 0.39f

static constexpr int TPB   = 256;
static constexpr int WARPS = TPB / 32;
static constexpr int ITEMS = 2;                  // edges per lane
static constexpr int EPW   = 32 * ITEMS;         // 64 edges per warp
static constexpr int EPB   = TPB * ITEMS;        // 512 edges per block

__global__ __launch_bounds__(TPB)
void polarisation_kernel(const int* __restrict__ edge_src,
                         const int* __restrict__ edge_dst,
                         const float* __restrict__ distances,
                         const float* __restrict__ vec,
                         const float* __restrict__ pol,
                         float* __restrict__ out,
                         int E) {
    // Warp-private slabs: EPW*9 = 576 floats = 144 float4 per warp. 18 KB/CTA.
    __shared__ float s_slab[WARPS][EPW * 9];

    const int lane = threadIdx.x & 31;
    const int wid  = threadIdx.x >> 5;
    const int block_start = blockIdx.x * EPB;
    const int wbase = block_start + wid * EPW;    // this warp's first edge

    const float inv_bohr = 1.0f / BOHR_F;
    const float inv_b6 = inv_bohr * inv_bohr * inv_bohr *
                         inv_bohr * inv_bohr * inv_bohr;

    float* slab = s_slab[wid];

    if (wbase + EPW <= E) {
        // ---------------- fast path (no CTA sync anywhere) ----------------
        const int e0 = wbase + lane;
        const int e1 = wbase + 32 + lane;

        // gather chain first (longest latency): idx then pol
        const int s0 = __ldcs(&edge_src[e0]);
        const int d0 = __ldcs(&edge_dst[e0]);
        const int s1 = __ldcs(&edge_src[e1]);
        const int d1 = __ldcs(&edge_dst[e1]);
        const float ps0 = __ldg(&pol[s0]);
        const float pd0 = __ldg(&pol[d0]);
        const float ps1 = __ldg(&pol[s1]);
        const float pd1 = __ldg(&pol[d1]);

        // independent streaming loads overlap the gather latency
        const float r0 = __ldcs(&distances[e0]);
        const float r1 = __ldcs(&distances[e1]);
        const float v0x = __ldcs(&vec[e0 * 3 + 0]);
        const float v0y = __ldcs(&vec[e0 * 3 + 1]);
        const float v0z = __ldcs(&vec[e0 * 3 + 2]);
        const float v1x = __ldcs(&vec[e1 * 3 + 0]);
        const float v1y = __ldcs(&vec[e1 * 3 + 1]);
        const float v1z = __ldcs(&vec[e1 * 3 + 2]);

        #pragma unroll
        for (int j = 0; j < ITEMS; j++) {
            const float r  = (j == 0 ? r0 : r1) * inv_bohr;
            const float vx = (j == 0 ? v0x : v1x) * inv_bohr;
            const float vy = (j == 0 ? v0y : v1y) * inv_bohr;
            const float vz = (j == 0 ? v0z : v1z) * inv_bohr;
            const float alpha_ij = (j == 0 ? ps0 * pd0 : ps1 * pd1) * inv_b6;

            const float inv_r  = __fdividef(1.0f, r);
            const float inv_r2 = inv_r * inv_r;
            const float inv_r3 = inv_r2 * inv_r;
            const float inv_r5 = inv_r3 * inv_r2;

            // a*u^3 = a * r^3 / sqrt(alpha_ij)
            const float au3 = A_MUTUAL_F * (r * r * r) * rsqrtf(alpha_ij);
            const float ex  = __expf(-au3);
            const float lambda3 = 1.0f - ex;
            const float lambda5 = 1.0f - (1.0f + au3) * ex;

            const float c5 = 3.0f * lambda5 * inv_r5;
            const float c3 = lambda3 * inv_r3;

            // stride-9 smem writes within the warp slab: gcd(9,32)=1 -> clean
            float* o = &slab[(j * 32 + lane) * 9];
            o[0] = c5 * vx * vx - c3;
            o[1] = c5 * vx * vy;
            o[2] = c5 * vx * vz;
            o[3] = c5 * vy * vx;
            o[4] = c5 * vy * vy - c3;
            o[5] = c5 * vy * vz;
            o[6] = c5 * vz * vx;
            o[7] = c5 * vz * vy;
            o[8] = c5 * vz * vz - c3;
        }

        __syncwarp();

        // warp-cooperative coalesced store: 144 contiguous float4
        {
            const float4* slab4 = (const float4*)slab;
            float4* out4 = (float4*)out;
            const long long gbase4 = (long long)wbase * 9 / 4;  // wbase%32==0
            #pragma unroll
            for (int k = 0; k < (EPW * 9 / 4 + 31) / 32; k++) {
                const int idx = lane + k * 32;
                if (idx < EPW * 9 / 4)
                    __stcs(&out4[gbase4 + idx], slab4[idx]);
            }
        }
    } else {
        // ---------------- tail path: direct scalar stores ----------------
        #pragma unroll
        for (int j = 0; j < ITEMS; j++) {
            const int e = wbase + j * 32 + lane;
            if (e < E) {
                const float r  = distances[e] * inv_bohr;
                const float vx = vec[e * 3 + 0] * inv_bohr;
                const float vy = vec[e * 3 + 1] * inv_bohr;
                const float vz = vec[e * 3 + 2] * inv_bohr;
                const float alpha_ij = __ldg(&pol[edge_src[e]]) *
                                       __ldg(&pol[edge_dst[e]]) * inv_b6;

                const float inv_r  = __fdividef(1.0f, r);
                const float inv_r2 = inv_r * inv_r;
                const float inv_r3 = inv_r2 * inv_r;
                const float inv_r5 = inv_r3 * inv_r2;

                const float au3 = A_MUTUAL_F * (r * r * r) * rsqrtf(alpha_ij);
                const float ex  = __expf(-au3);
                const float lambda3 = 1.0f - ex;
                const float lambda5 = 1.0f - (1.0f + au3) * ex;

                const float c5 = 3.0f * lambda5 * inv_r5;
                const float c3 = lambda3 * inv_r3;

                float* o = &out[(long long)e * 9];
                o[0] = c5 * vx * vx - c3;
                o[1] = c5 * vx * vy;
                o[2] = c5 * vx * vz;
                o[3] = c5 * vy * vx;
                o[4] = c5 * vy * vy - c3;
                o[5] = c5 * vy * vz;
                o[6] = c5 * vz * vx;
                o[7] = c5 * vz * vy;
                o[8] = c5 * vz * vz - c3;
            }
        }
    }
}

extern "C" void kernel_launch(void* const* d_in, const int* in_sizes, int n_in,
                              void* d_out, int out_size) {
    // metadata order: species, edge_src, edge_dst, distances, vec, polarisability
    const int*   edge_src = (const int*)d_in[1];
    const int*   edge_dst = (const int*)d_in[2];
    const float* dist     = (const float*)d_in[3];
    const float* vec      = (const float*)d_in[4];
    const float* pol      = (const float*)d_in[5];
    float* out = (float*)d_out;

    const int E = in_sizes[1];
    const int blocks = (E + EPB - 1) / EPB;
    polarisation_kernel<<<blocks, TPB>>>(edge_src, edge_dst, dist, vec, pol, out, E);
}